// round 4
// baseline (speedup 1.0000x reference)
#include <cuda_runtime.h>
#include <cstdint>

#define TT 2048
#define BB 64
#define II 256
#define HH 512
#define KK 768            // H + I, hx = [h, x]
#define NCTA 128
#define NTHR 256

// Scratch (device globals: allocation APIs are forbidden)
__device__ float g_xT[TT][II][BB];      // x transposed: [t][i][b]
__device__ float g_hT[2][HH][BB];       // hidden state, double buffered, [k][b]
__device__ unsigned g_flags[NCTA][32];  // per-CTA arrival flag, 128B stride

// smem: Wsd[KK][32] dup-packed + pres[4][16][64] + cs[4][64] + bs[16]
static const int SMEM_FLOATS = KK * 32 + 4 * 16 * 64 + 4 * 64 + 16;
static const int SMEM_BYTES = SMEM_FLOATS * 4;   // ~115 KB

// ---------------- helpers ----------------
__device__ __forceinline__ void fma2(unsigned long long& d, unsigned long long a,
                                     unsigned long long b) {
    asm volatile("fma.rn.f32x2 %0, %1, %2, %0;" : "+l"(d) : "l"(a), "l"(b));
}

// 16B L2-direct load (bypass L1: required for cross-SM h freshness).
// Non-volatile so ptxas can hoist/batch for MLP; barrier asm has "memory"
// clobbers that fence it.
__device__ __forceinline__ ulonglong2 ldcg128(const float* p) {
    ulonglong2 v;
    asm("ld.global.cg.v2.u64 {%0,%1}, [%2];" : "=l"(v.x), "=l"(v.y) : "l"(p));
    return v;
}

__device__ __forceinline__ float fast_sigmoid(float z) {
    return __fdividef(1.0f, 1.0f + __expf(-z));
}
__device__ __forceinline__ float fast_tanh(float z) {
    return __fdividef(2.0f, 1.0f + __expf(-2.0f * z)) - 1.0f;
}

// ---------------- init (runs every launch: resets state + flags) ----------------
__global__ void init_kernel() {
    int i = blockIdx.x * blockDim.x + threadIdx.x;
    if (i < HH * BB) (&g_hT[0][0][0])[i] = 0.0f;
    if (i < NCTA * 32) (&g_flags[0][0])[i] = 0u;
}

// ---------------- x transpose: x[t][b][i] -> g_xT[t][i][b] ----------------
__global__ void xT_kernel(const float* __restrict__ x) {
    __shared__ float tile[64][65];
    int t = blockIdx.x;
    for (int ic = 0; ic < 4; ++ic) {
        __syncthreads();
        for (int idx = threadIdx.x; idx < 4096; idx += blockDim.x) {
            int b = idx >> 6, i2 = idx & 63;
            tile[b][i2] = x[((size_t)t * BB + b) * II + ic * 64 + i2];
        }
        __syncthreads();
        for (int idx = threadIdx.x; idx < 4096; idx += blockDim.x) {
            int i2 = idx >> 6, b = idx & 63;
            g_xT[t][ic * 64 + i2][b] = tile[b][i2];
        }
    }
}

// ---------------- persistent LSTM ----------------
__global__ void __launch_bounds__(NTHR, 1) lstm_persist(
    const float* __restrict__ Wf, const float* __restrict__ bf,
    const float* __restrict__ Wi, const float* __restrict__ bi,
    const float* __restrict__ Wc, const float* __restrict__ bc,
    const float* __restrict__ Wo, const float* __restrict__ bo,
    float* __restrict__ out)
{
    extern __shared__ float sm[];
    float* Wsd  = sm;                     // [KK][32]  rows duplicated-packed for f32x2
    float* pres = Wsd + KK * 32;          // [4][16][64] partial pre-activations (per k-quarter)
    float* cs   = pres + 4 * 16 * 64;     // [4][64] cell state (this CTA's 4 hid units)
    float* bs   = cs + 4 * 64;            // [16] biases

    const int tid  = threadIdx.x;
    const int cta  = blockIdx.x;
    const int hid0 = cta * 4;             // 4 hidden units per CTA

    // Warp layout: all 4 row-groups inside one warp so each v-load is a
    // single 128B line broadcast 4-ways.
    const int lane = tid & 31;
    const int w    = tid >> 5;            // 0..7
    const int rg   = lane >> 3;           // 0..3 : rows 4rg .. 4rg+3
    const int bg   = (w & 1) * 8 + (lane & 7);  // 0..15: batches 4bg .. 4bg+3
    const int q    = w >> 1;              // k-quarter 0..3 within each 128-chunk

    // Load weights for this CTA's 16 gate rows: row r = g*4 + j  (g: f,i,c,o)
    // Duplicated-packed: Wsd[k*32 + 2r] = Wsd[k*32 + 2r + 1] = W[r][k]
    for (int idx = tid; idx < KK * 16; idx += NTHR) {
        int k = idx >> 4, r = idx & 15;
        int g = r >> 2, j = r & 3;
        const float* W = (g == 0) ? Wf : (g == 1) ? Wi : (g == 2) ? Wc : Wo;
        float wv = W[(size_t)(hid0 + j) * KK + k];
        Wsd[k * 32 + 2 * r]     = wv;
        Wsd[k * 32 + 2 * r + 1] = wv;
    }
    if (tid < 16) {
        int g = tid >> 2, j = tid & 3;
        const float* Bv = (g == 0) ? bf : (g == 1) ? bi : (g == 2) ? bc : bo;
        bs[tid] = Bv[hid0 + j];
    }
    for (int idx = tid; idx < 4 * 64; idx += NTHR) cs[idx] = 0.0f;
    __syncthreads();

    for (int t = 0; t < TT; ++t) {
        const float* hsrc = &g_hT[t & 1][0][0];
        const float* xsrc = &g_xT[t][0][0];

        unsigned long long a0 = 0, a1 = 0, a2 = 0, a3 = 0,
                           a4 = 0, a5 = 0, a6 = 0, a7 = 0;

        // h part: k = 0..511 (4 chunks of 128; this thread does kl = q*32 + i)
        #pragma unroll
        for (int c = 0; c < 4; ++c) {
            const float* vp = hsrc + (c * 128 + q * 32) * 64 + 4 * bg;
            const float* wp = Wsd + (c * 128 + q * 32) * 32 + 8 * rg;
            #pragma unroll 8
            for (int i = 0; i < 32; ++i) {
                ulonglong2 v  = ldcg128(vp + i * 64);
                ulonglong2 wA = *(const ulonglong2*)(wp + i * 32);      // rows 4rg,4rg+1 (dup)
                ulonglong2 wB = *(const ulonglong2*)(wp + i * 32 + 4);  // rows 4rg+2,4rg+3 (dup)
                fma2(a0, wA.x, v.x);  fma2(a1, wA.x, v.y);
                fma2(a2, wA.y, v.x);  fma2(a3, wA.y, v.y);
                fma2(a4, wB.x, v.x);  fma2(a5, wB.x, v.y);
                fma2(a6, wB.y, v.x);  fma2(a7, wB.y, v.y);
            }
        }
        // x part: k = 512..767 (2 chunks of 128)
        #pragma unroll
        for (int c = 0; c < 2; ++c) {
            const float* vp = xsrc + (c * 128 + q * 32) * 64 + 4 * bg;
            const float* wp = Wsd + ((4 + c) * 128 + q * 32) * 32 + 8 * rg;
            #pragma unroll 8
            for (int i = 0; i < 32; ++i) {
                ulonglong2 v  = ldcg128(vp + i * 64);
                ulonglong2 wA = *(const ulonglong2*)(wp + i * 32);
                ulonglong2 wB = *(const ulonglong2*)(wp + i * 32 + 4);
                fma2(a0, wA.x, v.x);  fma2(a1, wA.x, v.y);
                fma2(a2, wA.y, v.x);  fma2(a3, wA.y, v.y);
                fma2(a4, wB.x, v.x);  fma2(a5, wB.x, v.y);
                fma2(a6, wB.y, v.x);  fma2(a7, wB.y, v.y);
            }
        }

        // dump partial pre-activations: pres[q][row][b]
        {
            ulonglong2 p;
            p.x = a0; p.y = a1;
            *(ulonglong2*)(pres + (q * 16 + 4 * rg + 0) * 64 + 4 * bg) = p;
            p.x = a2; p.y = a3;
            *(ulonglong2*)(pres + (q * 16 + 4 * rg + 1) * 64 + 4 * bg) = p;
            p.x = a4; p.y = a5;
            *(ulonglong2*)(pres + (q * 16 + 4 * rg + 2) * 64 + 4 * bg) = p;
            p.x = a6; p.y = a7;
            *(ulonglong2*)(pres + (q * 16 + 4 * rg + 3) * 64 + 4 * bg) = p;
        }
        __syncthreads();

        // gates + state update: 256 cells, one per thread
        float* hdst = &g_hT[(t + 1) & 1][0][0];
        {
            int b = tid >> 2, j = tid & 3;
            float zf = bs[j],      zi = bs[4 + j],
                  zc = bs[8 + j],  zo = bs[12 + j];
            #pragma unroll
            for (int qq = 0; qq < 4; ++qq) {
                zf += pres[(qq * 16 + 0  + j) * 64 + b];
                zi += pres[(qq * 16 + 4  + j) * 64 + b];
                zc += pres[(qq * 16 + 8  + j) * 64 + b];
                zo += pres[(qq * 16 + 12 + j) * 64 + b];
            }
            float fg = fast_sigmoid(zf);
            float ig = fast_sigmoid(zi);
            float og = fast_sigmoid(zo);
            float cn = fg * cs[j * 64 + b] + ig * fast_tanh(zc);
            float hn = og * fast_tanh(cn);
            cs[j * 64 + b] = cn;
            hdst[(hid0 + j) * BB + b] = hn;
            out[((size_t)t * BB + b) * HH + hid0 + j] = hn;
            if (t == TT - 1) {
                out[(size_t)TT * BB * HH + (size_t)b * HH + hid0 + j] = hn;                    // h_last
                out[(size_t)TT * BB * HH + (size_t)BB * HH + (size_t)b * HH + hid0 + j] = cn;  // c_last
            }
        }

        // ---- grid barrier: per-CTA flags (distinct 128B lines), no atomics ----
        __threadfence();
        __syncthreads();
        if (tid == 0) {
            asm volatile("st.release.gpu.global.u32 [%0], %1;"
                         :: "l"(&g_flags[cta][0]), "r"((unsigned)(t + 1))
                         : "memory");
        }
        if (tid < NCTA) {
            const unsigned* fp = &g_flags[tid][0];
            unsigned v;
            do {
                asm volatile("ld.acquire.gpu.global.u32 %0, [%1];"
                             : "=r"(v) : "l"(fp) : "memory");
            } while (v < (unsigned)(t + 1));
        }
        __syncthreads();
    }
}

// ---------------- launch ----------------
extern "C" void kernel_launch(void* const* d_in, const int* in_sizes, int n_in,
                              void* d_out, int out_size) {
    const float* x  = (const float*)d_in[0];
    const float* Wf = (const float*)d_in[1];
    const float* bf = (const float*)d_in[2];
    const float* Wi = (const float*)d_in[3];
    const float* bi = (const float*)d_in[4];
    const float* Wc = (const float*)d_in[5];
    const float* bc = (const float*)d_in[6];
    const float* Wo = (const float*)d_in[7];
    const float* bo = (const float*)d_in[8];
    float* out = (float*)d_out;

    cudaFuncSetAttribute(lstm_persist,
                         cudaFuncAttributeMaxDynamicSharedMemorySize, SMEM_BYTES);

    init_kernel<<<(HH * BB + 255) / 256, 256>>>();
    xT_kernel<<<TT, 256>>>(x);
    lstm_persist<<<NCTA, NTHR, SMEM_BYTES>>>(Wf, bf, Wi, bi, Wc, bc, Wo, bo, out);
}

// round 5
// speedup vs baseline: 1.1899x; 1.1899x over previous
#include <cuda_runtime.h>
#include <cstdint>

#define TT 2048
#define BB 64
#define II 256
#define HH 512
#define KK 768            // H + I, hx = [h, x]
#define NCTA 128
#define NTHR 256
#define CHUNK_BYTES 32768 // 128 k-rows x 64 batch x 4B

// Scratch (device globals: allocation APIs are forbidden)
__device__ float g_xT[TT][II][BB];      // x transposed: [t][i][b]
__device__ float g_hT[2][HH][BB];       // hidden state, double buffered, [k][b]
__device__ unsigned g_flags[NCTA][32];  // per-CTA arrival flag, 128B stride

// smem layout (floats):
//   [0,32)                  mbar area (3 x 8B used), keeps buffers 128B-aligned
//   Wsd  [KK][32]           dup-packed weights            = 24576
//   bufs [3][128][64]       staged hx chunks (TMA ring)   = 24576
//   pres [4][16][64]        partial pre-activations       = 4096
//   cs   [4][64]            cell state                    = 256
//   bs   [16]               biases
static const int SMEM_FLOATS = 32 + KK * 32 + 3 * 128 * 64 + 4 * 16 * 64 + 4 * 64 + 16;
static const int SMEM_BYTES = SMEM_FLOATS * 4;   // 214,208 B

// ---------------- helpers ----------------
__device__ __forceinline__ void fma2(unsigned long long& d, unsigned long long a,
                                     unsigned long long b) {
    asm volatile("fma.rn.f32x2 %0, %1, %2, %0;" : "+l"(d) : "l"(a), "l"(b));
}

__device__ __forceinline__ unsigned smem_u32(const void* p) {
    return (unsigned)__cvta_generic_to_shared(p);
}

// One-shot 32KB bulk copy global->smem with mbarrier completion (issued by tid 0)
__device__ __forceinline__ void bulk_ld(float* dst_sm, const float* src, unsigned mbar) {
    unsigned d = smem_u32(dst_sm);
    asm volatile("mbarrier.arrive.expect_tx.shared.b64 _, [%0], %1;"
                 :: "r"(mbar), "r"((unsigned)CHUNK_BYTES) : "memory");
    asm volatile("cp.async.bulk.shared::cluster.global.mbarrier::complete_tx::bytes "
                 "[%0], [%1], %2, [%3];"
                 :: "r"(d), "l"(src), "r"((unsigned)CHUNK_BYTES), "r"(mbar) : "memory");
}

__device__ __forceinline__ void mbar_wait(unsigned mbar, unsigned parity) {
    asm volatile(
        "{\n\t"
        ".reg .pred P1;\n\t"
        "WAIT_LOOP_%=:\n\t"
        "mbarrier.try_wait.parity.acquire.cta.shared::cta.b64 P1, [%0], %1, 0x989680;\n\t"
        "@P1 bra.uni WAIT_DONE_%=;\n\t"
        "bra.uni WAIT_LOOP_%=;\n\t"
        "WAIT_DONE_%=:\n\t"
        "}"
        :: "r"(mbar), "r"(parity) : "memory");
}

__device__ __forceinline__ float fast_sigmoid(float z) {
    return __fdividef(1.0f, 1.0f + __expf(-z));
}
__device__ __forceinline__ float fast_tanh(float z) {
    return __fdividef(2.0f, 1.0f + __expf(-2.0f * z)) - 1.0f;
}

// ---------------- init (runs every launch: resets state + flags) ----------------
__global__ void init_kernel() {
    int i = blockIdx.x * blockDim.x + threadIdx.x;
    if (i < HH * BB) (&g_hT[0][0][0])[i] = 0.0f;
    if (i < NCTA * 32) (&g_flags[0][0])[i] = 0u;
}

// ---------------- x transpose: x[t][b][i] -> g_xT[t][i][b] ----------------
__global__ void xT_kernel(const float* __restrict__ x) {
    __shared__ float tile[64][65];
    int t = blockIdx.x;
    for (int ic = 0; ic < 4; ++ic) {
        __syncthreads();
        for (int idx = threadIdx.x; idx < 4096; idx += blockDim.x) {
            int b = idx >> 6, i2 = idx & 63;
            tile[b][i2] = x[((size_t)t * BB + b) * II + ic * 64 + i2];
        }
        __syncthreads();
        for (int idx = threadIdx.x; idx < 4096; idx += blockDim.x) {
            int i2 = idx >> 6, b = idx & 63;
            g_xT[t][ic * 64 + i2][b] = tile[b][i2];
        }
    }
}

// ---------------- persistent LSTM ----------------
__global__ void __launch_bounds__(NTHR, 1) lstm_persist(
    const float* __restrict__ Wf, const float* __restrict__ bf,
    const float* __restrict__ Wi, const float* __restrict__ bi,
    const float* __restrict__ Wc, const float* __restrict__ bc,
    const float* __restrict__ Wo, const float* __restrict__ bo,
    float* __restrict__ out)
{
    extern __shared__ float sm[];
    float* mbar_f = sm;                   // 3 mbarriers (8B each) in first 128B
    float* Wsd  = sm + 32;                // [KK][32]  rows duplicated-packed for f32x2
    float* bufs = Wsd + KK * 32;          // [3][128][64] TMA ring
    float* pres = bufs + 3 * 128 * 64;    // [4][16][64] partial pre-activations
    float* cs   = pres + 4 * 16 * 64;     // [4][64] cell state (this CTA's 4 hid units)
    float* bs   = cs + 4 * 64;            // [16] biases

    const unsigned mb0 = smem_u32(mbar_f);
    const unsigned mb[3] = { mb0, mb0 + 8, mb0 + 16 };

    const int tid  = threadIdx.x;
    const int cta  = blockIdx.x;
    const int hid0 = cta * 4;             // 4 hidden units per CTA
    const int q    = tid >> 6;            // k-quarter 0..3 (32 kl of each chunk)
    const int lq   = tid & 63;
    const int rg   = lq >> 4;             // 0..3 : rows 4rg .. 4rg+3
    const int bg   = lq & 15;             // 0..15: batches 4bg .. 4bg+3

    // Load weights for this CTA's 16 gate rows: row r = g*4 + j  (g: f,i,c,o)
    for (int idx = tid; idx < KK * 16; idx += NTHR) {
        int k = idx >> 4, r = idx & 15;
        int g = r >> 2, j = r & 3;
        const float* W = (g == 0) ? Wf : (g == 1) ? Wi : (g == 2) ? Wc : Wo;
        float wv = W[(size_t)(hid0 + j) * KK + k];
        Wsd[k * 32 + 2 * r]     = wv;
        Wsd[k * 32 + 2 * r + 1] = wv;
    }
    if (tid < 16) {
        int g = tid >> 2, j = tid & 3;
        const float* Bv = (g == 0) ? bf : (g == 1) ? bi : (g == 2) ? bc : bo;
        bs[tid] = Bv[hid0 + j];
    }
    for (int idx = tid; idx < 4 * 64; idx += NTHR) cs[idx] = 0.0f;
    if (tid == 0) {
        #pragma unroll
        for (int j = 0; j < 3; ++j)
            asm volatile("mbarrier.init.shared.b64 [%0], 1;" :: "r"(mb[j]) : "memory");
    }
    __syncthreads();

    unsigned ph0 = 0, ph1 = 0, ph2 = 0;   // mbar phase parity trackers

    for (int t = 0; t < TT; ++t) {
        const float* hsrc = &g_hT[t & 1][0][0];
        const float* xsrc = &g_xT[t][0][0];
        // chunk c source: c<4 -> h chunk c, else x chunk c-4
        const float* srcs[6] = { hsrc, hsrc + 8192, hsrc + 16384, hsrc + 24576,
                                 xsrc, xsrc + 8192 };

        // prefetch chunks 0,1,2 into ring (buffers free: last used 3 chunks ago)
        if (tid == 0) {
            asm volatile("fence.proxy.async;" ::: "memory");
            bulk_ld(bufs,               srcs[0], mb[0]);
            bulk_ld(bufs + 128 * 64,    srcs[1], mb[1]);
            bulk_ld(bufs + 2 * 128 * 64, srcs[2], mb[2]);
        }

        unsigned long long a0 = 0, a1 = 0, a2 = 0, a3 = 0,
                           a4 = 0, a5 = 0, a6 = 0, a7 = 0;

        #pragma unroll
        for (int c = 0; c < 6; ++c) {
            const int bsel = (c < 3) ? c : c - 3;        // ring slot = c % 3
            // wait chunk c
            if (bsel == 0)      { mbar_wait(mb[0], ph0); if (c == 0) {} }
            else if (bsel == 1) { mbar_wait(mb[1], ph1); }
            else                { mbar_wait(mb[2], ph2); }

            const float* hb = bufs + bsel * (128 * 64) + q * 32 * 64 + 4 * bg;
            const float* wb = Wsd + (c * 128 + q * 32) * 32 + 8 * rg;
            #pragma unroll 4
            for (int i = 0; i < 32; ++i) {
                ulonglong2 wA = *(const ulonglong2*)(wb + i * 32);        // rows 4rg,4rg+1 (dup)
                ulonglong2 wB = *(const ulonglong2*)(wb + i * 32 + 4);    // rows 4rg+2,4rg+3 (dup)
                ulonglong2 v  = *(const ulonglong2*)(hb + i * 64);        // batches 4bg..4bg+3
                fma2(a0, wA.x, v.x);  fma2(a1, wA.x, v.y);
                fma2(a2, wA.y, v.x);  fma2(a3, wA.y, v.y);
                fma2(a4, wB.x, v.x);  fma2(a5, wB.x, v.y);
                fma2(a6, wB.y, v.x);  fma2(a7, wB.y, v.y);
            }
            // flip parity for this mbar after consuming
            if (bsel == 0) ph0 ^= 1; else if (bsel == 1) ph1 ^= 1; else ph2 ^= 1;

            __syncthreads();   // all consumers done with this buffer
            if (c < 3 && tid == 0) {
                // refill this slot with chunk c+3
                bulk_ld(bufs + bsel * (128 * 64), srcs[c + 3], mb[bsel]);
            }
        }

        // dump partial pre-activations: pres[q][row][b]
        {
            ulonglong2 p;
            p.x = a0; p.y = a1;
            *(ulonglong2*)(pres + (q * 16 + 4 * rg + 0) * 64 + 4 * bg) = p;
            p.x = a2; p.y = a3;
            *(ulonglong2*)(pres + (q * 16 + 4 * rg + 1) * 64 + 4 * bg) = p;
            p.x = a4; p.y = a5;
            *(ulonglong2*)(pres + (q * 16 + 4 * rg + 2) * 64 + 4 * bg) = p;
            p.x = a6; p.y = a7;
            *(ulonglong2*)(pres + (q * 16 + 4 * rg + 3) * 64 + 4 * bg) = p;
        }
        __syncthreads();

        // gates + state update: 256 cells, one per thread
        float* hdst = &g_hT[(t + 1) & 1][0][0];
        {
            int b = tid >> 2, j = tid & 3;
            float zf = bs[j],      zi = bs[4 + j],
                  zc = bs[8 + j],  zo = bs[12 + j];
            #pragma unroll
            for (int qq = 0; qq < 4; ++qq) {
                zf += pres[(qq * 16 + 0  + j) * 64 + b];
                zi += pres[(qq * 16 + 4  + j) * 64 + b];
                zc += pres[(qq * 16 + 8  + j) * 64 + b];
                zo += pres[(qq * 16 + 12 + j) * 64 + b];
            }
            float fg = fast_sigmoid(zf);
            float ig = fast_sigmoid(zi);
            float og = fast_sigmoid(zo);
            float cn = fg * cs[j * 64 + b] + ig * fast_tanh(zc);
            float hn = og * fast_tanh(cn);
            cs[j * 64 + b] = cn;
            hdst[(hid0 + j) * BB + b] = hn;
            out[((size_t)t * BB + b) * HH + hid0 + j] = hn;
            if (t == TT - 1) {
                out[(size_t)TT * BB * HH + (size_t)b * HH + hid0 + j] = hn;                    // h_last
                out[(size_t)TT * BB * HH + (size_t)BB * HH + (size_t)b * HH + hid0 + j] = cn;  // c_last
            }
        }

        // ---- grid barrier: per-CTA flags (distinct 128B lines), no atomics ----
        __threadfence();
        __syncthreads();
        if (tid == 0) {
            asm volatile("st.release.gpu.global.u32 [%0], %1;"
                         :: "l"(&g_flags[cta][0]), "r"((unsigned)(t + 1))
                         : "memory");
        }
        if (tid < NCTA) {
            const unsigned* fp = &g_flags[tid][0];
            unsigned v;
            do {
                asm volatile("ld.acquire.gpu.global.u32 %0, [%1];"
                             : "=r"(v) : "l"(fp) : "memory");
            } while (v < (unsigned)(t + 1));
        }
        __syncthreads();
    }
}

// ---------------- launch ----------------
extern "C" void kernel_launch(void* const* d_in, const int* in_sizes, int n_in,
                              void* d_out, int out_size) {
    const float* x  = (const float*)d_in[0];
    const float* Wf = (const float*)d_in[1];
    const float* bf = (const float*)d_in[2];
    const float* Wi = (const float*)d_in[3];
    const float* bi = (const float*)d_in[4];
    const float* Wc = (const float*)d_in[5];
    const float* bc = (const float*)d_in[6];
    const float* Wo = (const float*)d_in[7];
    const float* bo = (const float*)d_in[8];
    float* out = (float*)d_out;

    cudaFuncSetAttribute(lstm_persist,
                         cudaFuncAttributeMaxDynamicSharedMemorySize, SMEM_BYTES);

    init_kernel<<<(HH * BB + 255) / 256, 256>>>();
    xT_kernel<<<TT, 256>>>(x);
    lstm_persist<<<NCTA, NTHR, SMEM_BYTES>>>(Wf, bf, Wi, bi, Wc, bc, Wo, bo, out);
}

// round 6
// speedup vs baseline: 1.3267x; 1.1149x over previous
#include <cuda_runtime.h>
#include <cstdint>

#define TT 2048
#define BB 64
#define II 256
#define HH 512
#define KK 768            // H + I, hx = [h, x]
#define NCTA 128
#define NTHR 256
#define CHUNK_BYTES 32768 // 128 k-rows x 64 batch x 4B
#define CH (128 * 64)     // floats per chunk

// Scratch (device globals: allocation APIs are forbidden)
__device__ float g_xT[TT][II][BB];      // x transposed: [t][i][b]
__device__ float g_hT[2][HH][BB];       // hidden state, double buffered, [k][b]
__device__ unsigned g_flags[NCTA][32];  // per-CTA arrival flag, 128B stride

static const int SMEM_FLOATS = 32 + KK * 32 + 3 * CH + 4 * 16 * 64 + 4 * 64 + 16;
static const int SMEM_BYTES = SMEM_FLOATS * 4;   // 214,208 B

// ---------------- helpers ----------------
__device__ __forceinline__ void fma2(unsigned long long& d, unsigned long long a,
                                     unsigned long long b) {
    asm volatile("fma.rn.f32x2 %0, %1, %2, %0;" : "+l"(d) : "l"(a), "l"(b));
}

__device__ __forceinline__ unsigned smem_u32(const void* p) {
    return (unsigned)__cvta_generic_to_shared(p);
}

// One-shot 32KB bulk copy global->smem with mbarrier completion (issued by tid 0)
__device__ __forceinline__ void bulk_ld(float* dst_sm, const float* src, unsigned mbar) {
    unsigned d = smem_u32(dst_sm);
    asm volatile("mbarrier.arrive.expect_tx.shared.b64 _, [%0], %1;"
                 :: "r"(mbar), "r"((unsigned)CHUNK_BYTES) : "memory");
    asm volatile("cp.async.bulk.shared::cluster.global.mbarrier::complete_tx::bytes "
                 "[%0], [%1], %2, [%3];"
                 :: "r"(d), "l"(src), "r"((unsigned)CHUNK_BYTES), "r"(mbar) : "memory");
}

__device__ __forceinline__ void mbar_wait(unsigned mbar, unsigned parity) {
    asm volatile(
        "{\n\t"
        ".reg .pred P1;\n\t"
        "WAIT_LOOP_%=:\n\t"
        "mbarrier.try_wait.parity.acquire.cta.shared::cta.b64 P1, [%0], %1, 0x989680;\n\t"
        "@P1 bra.uni WAIT_DONE_%=;\n\t"
        "bra.uni WAIT_LOOP_%=;\n\t"
        "WAIT_DONE_%=:\n\t"
        "}"
        :: "r"(mbar), "r"(parity) : "memory");
}

__device__ __forceinline__ float fast_sigmoid(float z) {
    return __fdividef(1.0f, 1.0f + __expf(-z));
}
__device__ __forceinline__ float fast_tanh(float z) {
    return __fdividef(2.0f, 1.0f + __expf(-2.0f * z)) - 1.0f;
}

// ---------------- init (runs every launch: resets state + flags) ----------------
__global__ void init_kernel() {
    int i = blockIdx.x * blockDim.x + threadIdx.x;
    if (i < HH * BB) (&g_hT[0][0][0])[i] = 0.0f;
    if (i < NCTA * 32) (&g_flags[0][0])[i] = 0u;
}

// ---------------- x transpose: x[t][b][i] -> g_xT[t][i][b] ----------------
__global__ void xT_kernel(const float* __restrict__ x) {
    __shared__ float tile[64][65];
    int t = blockIdx.x;
    for (int ic = 0; ic < 4; ++ic) {
        __syncthreads();
        for (int idx = threadIdx.x; idx < 4096; idx += blockDim.x) {
            int b = idx >> 6, i2 = idx & 63;
            tile[b][i2] = x[((size_t)t * BB + b) * II + ic * 64 + i2];
        }
        __syncthreads();
        for (int idx = threadIdx.x; idx < 4096; idx += blockDim.x) {
            int i2 = idx >> 6, b = idx & 63;
            g_xT[t][ic * 64 + i2][b] = tile[b][i2];
        }
    }
}

// chunk compute: kl = q*32 + i within chunk CIDX (weight row block)
#define COMPUTE(BUF, CIDX) do {                                              \
    const float* hb = (BUF) + q * 32 * 64 + 4 * bg;                          \
    const float* wb = Wsd + ((CIDX) * 128 + q * 32) * 32 + 8 * rg;           \
    _Pragma("unroll 4")                                                      \
    for (int i = 0; i < 32; ++i) {                                           \
        ulonglong2 wA = *(const ulonglong2*)(wb + i * 32);                   \
        ulonglong2 wB = *(const ulonglong2*)(wb + i * 32 + 4);               \
        ulonglong2 v  = *(const ulonglong2*)(hb + i * 64);                   \
        fma2(a0, wA.x, v.x);  fma2(a1, wA.x, v.y);                           \
        fma2(a2, wA.y, v.x);  fma2(a3, wA.y, v.y);                           \
        fma2(a4, wB.x, v.x);  fma2(a5, wB.x, v.y);                           \
        fma2(a6, wB.y, v.x);  fma2(a7, wB.y, v.y);                           \
    }                                                                        \
} while (0)

// ---------------- persistent LSTM ----------------
__global__ void __launch_bounds__(NTHR, 1) lstm_persist(
    const float* __restrict__ Wf, const float* __restrict__ bf,
    const float* __restrict__ Wi, const float* __restrict__ bi,
    const float* __restrict__ Wc, const float* __restrict__ bc,
    const float* __restrict__ Wo, const float* __restrict__ bo,
    float* __restrict__ out)
{
    extern __shared__ float sm[];
    float* mbar_f = sm;                   // 3 mbarriers (8B each) in first 128B
    float* Wsd  = sm + 32;                // [KK][32]  rows duplicated-packed for f32x2
    float* bufs = Wsd + KK * 32;          // [3][128][64] chunk ring
    float* pres = bufs + 3 * CH;          // [4][16][64] partial pre-activations
    float* cs   = pres + 4 * 16 * 64;     // [4][64] cell state (this CTA's 4 hid units)
    float* bs   = cs + 4 * 64;            // [16] biases

    const unsigned mb0 = smem_u32(mbar_f);
    const unsigned mb[3] = { mb0, mb0 + 8, mb0 + 16 };

    const int tid  = threadIdx.x;
    const int cta  = blockIdx.x;
    const int hid0 = cta * 4;             // 4 hidden units per CTA
    const int q    = tid >> 6;            // k-quarter 0..3 (32 kl of each chunk)
    const int lq   = tid & 63;
    const int rg   = lq >> 4;             // 0..3 : rows 4rg .. 4rg+3
    const int bg   = lq & 15;             // 0..15: batches 4bg .. 4bg+3

    // Load weights for this CTA's 16 gate rows: row r = g*4 + j  (g: f,i,c,o)
    for (int idx = tid; idx < KK * 16; idx += NTHR) {
        int k = idx >> 4, r = idx & 15;
        int g = r >> 2, j = r & 3;
        const float* W = (g == 0) ? Wf : (g == 1) ? Wi : (g == 2) ? Wc : Wo;
        float wv = W[(size_t)(hid0 + j) * KK + k];
        Wsd[k * 32 + 2 * r]     = wv;
        Wsd[k * 32 + 2 * r + 1] = wv;
    }
    if (tid < 16) {
        int g = tid >> 2, j = tid & 3;
        const float* Bv = (g == 0) ? bf : (g == 1) ? bi : (g == 2) ? bc : bo;
        bs[tid] = Bv[hid0 + j];
    }
    for (int idx = tid; idx < 4 * 64; idx += NTHR) cs[idx] = 0.0f;
    if (tid == 0) {
        #pragma unroll
        for (int j = 0; j < 3; ++j)
            asm volatile("mbarrier.init.shared.b64 [%0], 1;" :: "r"(mb[j]) : "memory");
    }
    __syncthreads();

    // prologue: prefetch x chunks of t=0 (x0 -> s0, x1 -> s1)
    if (tid == 0) {
        asm volatile("fence.proxy.async;" ::: "memory");
        bulk_ld(bufs + 0 * CH, &g_xT[0][0][0], mb[0]);
        bulk_ld(bufs + 1 * CH, &g_xT[0][0][0] + 8192, mb[1]);
    }

    for (int t = 0; t < TT; ++t) {
        const float* hsrc = &g_hT[t & 1][0][0];

        unsigned long long a0 = 0, a1 = 0, a2 = 0, a3 = 0,
                           a4 = 0, a5 = 0, a6 = 0, a7 = 0;

        // ---- x0 (slot0, parity 0): weights chunk 4 ----
        mbar_wait(mb[0], 0);
        COMPUTE(bufs + 0 * CH, 4);

        // ---- warp 0 polls the grid barrier (h(t) globally ready) ----
        if (tid < 32) {
            const unsigned need = (unsigned)t;
            bool ok;
            do {
                ok = true;
                #pragma unroll
                for (int j = 0; j < 4; ++j) {
                    unsigned v;
                    asm volatile("ld.acquire.gpu.global.u32 %0, [%1];"
                                 : "=r"(v) : "l"(&g_flags[tid * 4 + j][0]) : "memory");
                    ok &= (v >= need);
                }
            } while (!__all_sync(0xffffffffu, ok));
        }
        if (tid == 0) bulk_ld(bufs + 2 * CH, hsrc, mb[2]);          // h0 -> s2

        // ---- x1 (slot1, parity 0): weights chunk 5 ----
        mbar_wait(mb[1], 0);
        COMPUTE(bufs + 1 * CH, 5);
        __syncthreads();    // all x consumers done -> s0/s1 reusable
        if (tid == 0) {
            bulk_ld(bufs + 0 * CH, hsrc + 8192,  mb[0]);            // h1 -> s0
            bulk_ld(bufs + 1 * CH, hsrc + 16384, mb[1]);            // h2 -> s1
        }

        // ---- h0 (slot2, parity 0): weights chunk 0 ----
        mbar_wait(mb[2], 0);
        COMPUTE(bufs + 2 * CH, 0);
        __syncthreads();    // h0 consumers done -> s2 reusable
        if (tid == 0) bulk_ld(bufs + 2 * CH, hsrc + 24576, mb[2]);  // h3 -> s2

        // ---- h1 (slot0, parity 1): weights chunk 1 ----
        mbar_wait(mb[0], 1);
        COMPUTE(bufs + 0 * CH, 1);
        // ---- h2 (slot1, parity 1): weights chunk 2 ----
        mbar_wait(mb[1], 1);
        COMPUTE(bufs + 1 * CH, 2);
        // ---- h3 (slot2, parity 1): weights chunk 3 ----
        mbar_wait(mb[2], 1);
        COMPUTE(bufs + 2 * CH, 3);

        // dump partial pre-activations: pres[q][row][b]
        {
            ulonglong2 p;
            p.x = a0; p.y = a1;
            *(ulonglong2*)(pres + (q * 16 + 4 * rg + 0) * 64 + 4 * bg) = p;
            p.x = a2; p.y = a3;
            *(ulonglong2*)(pres + (q * 16 + 4 * rg + 1) * 64 + 4 * bg) = p;
            p.x = a4; p.y = a5;
            *(ulonglong2*)(pres + (q * 16 + 4 * rg + 2) * 64 + 4 * bg) = p;
            p.x = a6; p.y = a7;
            *(ulonglong2*)(pres + (q * 16 + 4 * rg + 3) * 64 + 4 * bg) = p;
        }
        __syncthreads();    // pres complete; also: all h1/h2/h3 consumption done

        // prefetch next step's x chunks into s0/s1 (TMA runs under gates+flag+poll)
        if (tid == 0 && t + 1 < TT) {
            const float* xn = &g_xT[t + 1][0][0];
            bulk_ld(bufs + 0 * CH, xn,        mb[0]);
            bulk_ld(bufs + 1 * CH, xn + 8192, mb[1]);
        }

        // gates + state update: 256 cells, one per thread
        float* hdst = &g_hT[(t + 1) & 1][0][0];
        {
            int b = tid >> 2, j = tid & 3;
            float zf = bs[j],      zi = bs[4 + j],
                  zc = bs[8 + j],  zo = bs[12 + j];
            #pragma unroll
            for (int qq = 0; qq < 4; ++qq) {
                zf += pres[(qq * 16 + 0  + j) * 64 + b];
                zi += pres[(qq * 16 + 4  + j) * 64 + b];
                zc += pres[(qq * 16 + 8  + j) * 64 + b];
                zo += pres[(qq * 16 + 12 + j) * 64 + b];
            }
            float fg = fast_sigmoid(zf);
            float ig = fast_sigmoid(zi);
            float og = fast_sigmoid(zo);
            float cn = fg * cs[j * 64 + b] + ig * fast_tanh(zc);
            float hn = og * fast_tanh(cn);
            cs[j * 64 + b] = cn;
            hdst[(hid0 + j) * BB + b] = hn;
            out[((size_t)t * BB + b) * HH + hid0 + j] = hn;
            if (t == TT - 1) {
                out[(size_t)TT * BB * HH + (size_t)b * HH + hid0 + j] = hn;                    // h_last
                out[(size_t)TT * BB * HH + (size_t)BB * HH + (size_t)b * HH + hid0 + j] = cn;  // c_last
            }
        }

        // publish this CTA's arrival for step t+1
        __threadfence();
        __syncthreads();
        if (tid == 0) {
            asm volatile("st.release.gpu.global.u32 [%0], %1;"
                         :: "l"(&g_flags[cta][0]), "r"((unsigned)(t + 1))
                         : "memory");
        }
    }
}

// ---------------- launch ----------------
extern "C" void kernel_launch(void* const* d_in, const int* in_sizes, int n_in,
                              void* d_out, int out_size) {
    const float* x  = (const float*)d_in[0];
    const float* Wf = (const float*)d_in[1];
    const float* bf = (const float*)d_in[2];
    const float* Wi = (const float*)d_in[3];
    const float* bi = (const float*)d_in[4];
    const float* Wc = (const float*)d_in[5];
    const float* bc = (const float*)d_in[6];
    const float* Wo = (const float*)d_in[7];
    const float* bo = (const float*)d_in[8];
    float* out = (float*)d_out;

    cudaFuncSetAttribute(lstm_persist,
                         cudaFuncAttributeMaxDynamicSharedMemorySize, SMEM_BYTES);

    init_kernel<<<(HH * BB + 255) / 256, 256>>>();
    xT_kernel<<<TT, 256>>>(x);
    lstm_persist<<<NCTA, NTHR, SMEM_BYTES>>>(Wf, bf, Wi, bi, Wc, bc, Wo, bo, out);
}